// round 2
// baseline (speedup 1.0000x reference)
#include <cuda_runtime.h>
#include <math.h>

#define Nn 50000
#define Ee 800000
#define ET (Ee + Nn)      // edges + self loops
#define DIN 256
#define HC 128            // H*C layer1 width
#define OUT2 32
#define Dts 128
#define LAT 16

// output layout (floats)
#define OFF_CAUS   0
#define OFF_Z      (Nn*32)
#define OFF_MEAN   (Nn*48)
#define OFF_LOGVAR (Nn*64)
#define OFF_XREC   (Nn*80)
#define OFF_REG    (Nn*208)

// ---------------- scratch (static device globals; no allocation) -------------
__device__ float g_x[(size_t)Nn * DIN];       // concat input [N,256]
__device__ float g_xl1[(size_t)Nn * HC];
__device__ float g_xr1[(size_t)Nn * HC];
__device__ float g_out1[(size_t)Nn * HC];     // layer1 accum -> h after relu+bias
__device__ float g_e[(size_t)ET * 4];         // edge scores (layer1: [ET,4]; layer2 reuses [ET])
__device__ float g_emax1[Nn * 4];
__device__ float g_den1[Nn * 4];
__device__ float g_xl2[Nn * OUT2];
__device__ float g_xr2[Nn * OUT2];
__device__ float g_emax2[Nn];
__device__ float g_den2[Nn];

__device__ __forceinline__ float lrelu(float v) { return v > 0.f ? v : 0.2f * v; }

__device__ __forceinline__ void atomicMaxFloat(float* addr, float value) {
    if (value >= 0.f)
        atomicMax((int*)addr, __float_as_int(value));
    else
        atomicMin((unsigned int*)addr, __float_as_uint(value));
}

// ---------------- init ----------------
__global__ void init_kernel(float* out) {
    int i = blockIdx.x * blockDim.x + threadIdx.x;
    if (i < Nn * HC) g_out1[i] = 0.f;
    if (i < Nn * 4) { g_den1[i] = 0.f; g_emax1[i] = -INFINITY; }
    if (i < Nn)     { g_den2[i] = 0.f; g_emax2[i] = -INFINITY; }
    if (i < Nn * 32) out[OFF_CAUS + i] = 0.f;
    if (i == 0) out[OFF_REG] = 0.f;
}

// ---------------- build concat input ----------------
__global__ void build_x(const float* __restrict__ ts, const float* __restrict__ ent_tab,
                        const float* __restrict__ tst_tab, const int* __restrict__ ent_idx,
                        const int* __restrict__ tst_idx) {
    int i = blockIdx.x * blockDim.x + threadIdx.x;
    if (i >= Nn * DIN) return;
    int n = i >> 8;          // /256
    int c = i & 255;
    float v;
    if (c < 128)       v = ts[n * 128 + c];
    else if (c < 192)  v = ent_tab[ent_idx[n] * 64 + (c - 128)];
    else               v = tst_tab[tst_idx[n] * 64 + (c - 192)];
    g_x[i] = v;
}

// ---------------- tiled fp32 GEMM: C[M,Nc] = A[M,K] @ W[K,Nc] + bias ----------
template <int BM, int BN, int BK, int TM, int TN>
__global__ void gemm_bias(const float* __restrict__ A, const float* __restrict__ W,
                          const float* __restrict__ bias, float* __restrict__ C,
                          int M, int K, int Nc) {
    __shared__ float As[BK][BM + 4];
    __shared__ float Ws[BK][BN];
    const int tid = threadIdx.x;
    const int NTX = BN / TN;
    const int tx = tid % NTX;
    const int ty = tid / NTX;
    const int row0 = blockIdx.y * BM;
    const int col0 = blockIdx.x * BN;
    float acc[TM][TN];
#pragma unroll
    for (int i = 0; i < TM; i++)
#pragma unroll
        for (int j = 0; j < TN; j++) acc[i][j] = 0.f;

    for (int k0 = 0; k0 < K; k0 += BK) {
        for (int i = tid; i < BM * BK; i += blockDim.x) {
            int c = i % BK, r = i / BK;
            int row = row0 + r;
            As[c][r] = (row < M) ? A[(size_t)row * K + k0 + c] : 0.f;
        }
        for (int i = tid; i < BK * BN; i += blockDim.x) {
            int r = i / BN, c = i % BN;
            Ws[r][c] = W[(size_t)(k0 + r) * Nc + col0 + c];
        }
        __syncthreads();
#pragma unroll
        for (int kk = 0; kk < BK; kk++) {
            float a[TM], b[TN];
#pragma unroll
            for (int i = 0; i < TM; i++) a[i] = As[kk][ty * TM + i];
#pragma unroll
            for (int j = 0; j < TN; j++) b[j] = Ws[kk][tx * TN + j];
#pragma unroll
            for (int i = 0; i < TM; i++)
#pragma unroll
                for (int j = 0; j < TN; j++) acc[i][j] += a[i] * b[j];
        }
        __syncthreads();
    }
#pragma unroll
    for (int i = 0; i < TM; i++) {
        int row = row0 + ty * TM + i;
        if (row < M) {
#pragma unroll
            for (int j = 0; j < TN; j++) {
                int col = col0 + tx * TN + j;
                C[(size_t)row * Nc + col] = acc[i][j] + bias[col];
            }
        }
    }
}

// ---------------- layer-1 edge kernels (warp per edge) ----------------
__global__ void edge_e1(const int* __restrict__ ei, const float* __restrict__ att1) {
    int w = (blockIdx.x * blockDim.x + threadIdx.x) >> 5;
    int lane = threadIdx.x & 31;
    if (w >= ET) return;
    int s, d;
    if (w < Ee) { s = ei[w]; d = ei[Ee + w]; } else { s = w - Ee; d = s; }
    float4 xl = *(const float4*)&g_xl1[(size_t)s * HC + lane * 4];
    float4 xr = *(const float4*)&g_xr1[(size_t)d * HC + lane * 4];
    float4 av = *(const float4*)&att1[lane * 4];   // att1 flat [h*32+c] == dim index
    float p = lrelu(xl.x + xr.x) * av.x + lrelu(xl.y + xr.y) * av.y +
              lrelu(xl.z + xr.z) * av.z + lrelu(xl.w + xr.w) * av.w;
    p += __shfl_down_sync(0xffffffff, p, 4);
    p += __shfl_down_sync(0xffffffff, p, 2);
    p += __shfl_down_sync(0xffffffff, p, 1);
    if ((lane & 7) == 0) {
        int h = lane >> 3;
        g_e[(size_t)w * 4 + h] = p;
        atomicMaxFloat(&g_emax1[d * 4 + h], p);
    }
}

__global__ void exp1(const int* __restrict__ ei) {
    int i = blockIdx.x * blockDim.x + threadIdx.x;
    if (i >= ET * 4) return;
    int eidx = i >> 2, h = i & 3;
    int d = (eidx < Ee) ? ei[Ee + eidx] : eidx - Ee;
    float a = expf(g_e[i] - g_emax1[d * 4 + h]);
    g_e[i] = a;
    atomicAdd(&g_den1[d * 4 + h], a);
}

__global__ void agg1(const int* __restrict__ ei) {
    int w = (blockIdx.x * blockDim.x + threadIdx.x) >> 5;
    int lane = threadIdx.x & 31;
    if (w >= ET) return;
    int s, d;
    if (w < Ee) { s = ei[w]; d = ei[Ee + w]; } else { s = w - Ee; d = s; }
    int h = lane >> 3;
    float alpha = g_e[(size_t)w * 4 + h] / g_den1[d * 4 + h];
    float4 xl = *(const float4*)&g_xl1[(size_t)s * HC + lane * 4];
    float* o = &g_out1[(size_t)d * HC + lane * 4];
    atomicAdd(o + 0, alpha * xl.x);
    atomicAdd(o + 1, alpha * xl.y);
    atomicAdd(o + 2, alpha * xl.z);
    atomicAdd(o + 3, alpha * xl.w);
}

__global__ void relu_bias1(const float* __restrict__ bias1) {
    int i = blockIdx.x * blockDim.x + threadIdx.x;
    if (i >= Nn * HC) return;
    float v = g_out1[i] + bias1[i & 127];
    g_out1[i] = v > 0.f ? v : 0.f;
}

// ---------------- layer-2 edge kernels ----------------
__global__ void edge_e2(const int* __restrict__ ei, const float* __restrict__ att2) {
    int w = (blockIdx.x * blockDim.x + threadIdx.x) >> 5;
    int lane = threadIdx.x & 31;
    if (w >= ET) return;
    int s, d;
    if (w < Ee) { s = ei[w]; d = ei[Ee + w]; } else { s = w - Ee; d = s; }
    float p = lrelu(g_xl2[s * 32 + lane] + g_xr2[d * 32 + lane]) * att2[lane];
#pragma unroll
    for (int off = 16; off; off >>= 1) p += __shfl_down_sync(0xffffffff, p, off);
    if (lane == 0) {
        g_e[w] = p;
        atomicMaxFloat(&g_emax2[d], p);
    }
}

__global__ void exp2(const int* __restrict__ ei) {
    int i = blockIdx.x * blockDim.x + threadIdx.x;
    if (i >= ET) return;
    int d = (i < Ee) ? ei[Ee + i] : i - Ee;
    float a = expf(g_e[i] - g_emax2[d]);
    g_e[i] = a;
    atomicAdd(&g_den2[d], a);
}

__global__ void agg2(const int* __restrict__ ei, float* __restrict__ caus) {
    int w = (blockIdx.x * blockDim.x + threadIdx.x) >> 5;
    int lane = threadIdx.x & 31;
    if (w >= ET) return;
    int s, d;
    if (w < Ee) { s = ei[w]; d = ei[Ee + w]; } else { s = w - Ee; d = s; }
    float alpha = g_e[w] / g_den2[d];
    atomicAdd(&caus[d * 32 + lane], alpha * g_xl2[s * 32 + lane]);
}

// ---------------- bias2 + regularization ----------------
__global__ void bias_reg(float* __restrict__ caus, const float* __restrict__ bias2,
                         float* __restrict__ reg) {
    __shared__ float sdata[8];
    int i = blockIdx.x * blockDim.x + threadIdx.x;
    float s = 0.f;
    if (i < Nn * 32) {
        float v = caus[i] + bias2[i & 31];
        caus[i] = v;
        s = v * v;
    }
#pragma unroll
    for (int off = 16; off; off >>= 1) s += __shfl_down_sync(0xffffffff, s, off);
    if ((threadIdx.x & 31) == 0) sdata[threadIdx.x >> 5] = s;
    __syncthreads();
    if (threadIdx.x < 8) {
        float t = sdata[threadIdx.x];
#pragma unroll
        for (int off = 4; off; off >>= 1) t += __shfl_down_sync(0xff, t, off);
        if (threadIdx.x == 0) atomicAdd(reg, 0.01f * t);
    }
}

// ---------------- VAE (thread per node, weights in shared) ----------------
__global__ void vae_kernel(const float* __restrict__ ts, const float* __restrict__ eps,
                           const float* __restrict__ We1, const float* __restrict__ be1,
                           const float* __restrict__ We2, const float* __restrict__ be2,
                           const float* __restrict__ Wd1, const float* __restrict__ bd1,
                           const float* __restrict__ Wd2, const float* __restrict__ bd2,
                           float* __restrict__ out) {
    __shared__ float sWe1[128 * 32];
    __shared__ float sWe2[32 * 32];
    __shared__ float sWd1[16 * 32];
    __shared__ float sWd2[32 * 128];
    __shared__ float sbe1[32], sbe2[32], sbd1[32], sbd2[128];
    int tid = threadIdx.x;
    for (int i = tid; i < 128 * 32; i += blockDim.x) sWe1[i] = We1[i];
    for (int i = tid; i < 32 * 32; i += blockDim.x) sWe2[i] = We2[i];
    for (int i = tid; i < 16 * 32; i += blockDim.x) sWd1[i] = Wd1[i];
    for (int i = tid; i < 32 * 128; i += blockDim.x) sWd2[i] = Wd2[i];
    if (tid < 32) { sbe1[tid] = be1[tid]; sbe2[tid] = be2[tid]; sbd1[tid] = bd1[tid]; }
    for (int i = tid; i < 128; i += blockDim.x) sbd2[i] = bd2[i];
    __syncthreads();

    int node = blockIdx.x * blockDim.x + tid;
    if (node >= Nn) return;

    float h1[32];
#pragma unroll
    for (int j = 0; j < 32; j++) h1[j] = sbe1[j];
    const float* tsrow = ts + (size_t)node * 128;
    for (int k = 0; k < 128; k++) {
        float t = tsrow[k];
#pragma unroll
        for (int j = 0; j < 32; j++) h1[j] += t * sWe1[k * 32 + j];
    }
#pragma unroll
    for (int j = 0; j < 32; j++) h1[j] = h1[j] > 0.f ? h1[j] : 0.f;

    float q[32];
#pragma unroll
    for (int j = 0; j < 32; j++) q[j] = sbe2[j];
#pragma unroll
    for (int k = 0; k < 32; k++) {
        float t = h1[k];
#pragma unroll
        for (int j = 0; j < 32; j++) q[j] += t * sWe2[k * 32 + j];
    }

    float z[16];
#pragma unroll
    for (int l = 0; l < 16; l++) {
        float mean = q[l], lv = q[16 + l];
        float std = expf(0.5f * lv);
        z[l] = mean + std * eps[(size_t)node * 16 + l];
        out[OFF_MEAN + node * 16 + l] = mean;
        out[OFF_LOGVAR + node * 16 + l] = lv;
        out[OFF_Z + node * 16 + l] = z[l];
    }

    float h2[32];
#pragma unroll
    for (int j = 0; j < 32; j++) h2[j] = sbd1[j];
#pragma unroll
    for (int k = 0; k < 16; k++) {
        float t = z[k];
#pragma unroll
        for (int j = 0; j < 32; j++) h2[j] += t * sWd1[k * 32 + j];
    }
#pragma unroll
    for (int j = 0; j < 32; j++) h2[j] = h2[j] > 0.f ? h2[j] : 0.f;

    float* xr = out + OFF_XREC + (size_t)node * 128;
    for (int j = 0; j < 128; j++) {
        float acc = sbd2[j];
#pragma unroll
        for (int k = 0; k < 32; k++) acc += h2[k] * sWd2[k * 128 + j];
        xr[j] = acc;
    }
}

// ---------------- launch ----------------
extern "C" void kernel_launch(void* const* d_in, const int* in_sizes, int n_in,
                              void* d_out, int out_size) {
    const float* ts      = (const float*)d_in[0];
    const float* eps     = (const float*)d_in[1];
    const float* ent_tab = (const float*)d_in[2];
    const float* tst_tab = (const float*)d_in[3];
    const float* Wl1  = (const float*)d_in[4];
    const float* bl1  = (const float*)d_in[5];
    const float* Wr1  = (const float*)d_in[6];
    const float* br1  = (const float*)d_in[7];
    const float* att1 = (const float*)d_in[8];
    const float* bias1= (const float*)d_in[9];
    const float* Wl2  = (const float*)d_in[10];
    const float* bl2  = (const float*)d_in[11];
    const float* Wr2  = (const float*)d_in[12];
    const float* br2  = (const float*)d_in[13];
    const float* att2 = (const float*)d_in[14];
    const float* bias2= (const float*)d_in[15];
    const float* We1  = (const float*)d_in[16];
    const float* be1  = (const float*)d_in[17];
    const float* We2  = (const float*)d_in[18];
    const float* be2  = (const float*)d_in[19];
    const float* Wd1  = (const float*)d_in[20];
    const float* bd1  = (const float*)d_in[21];
    const float* Wd2  = (const float*)d_in[22];
    const float* bd2  = (const float*)d_in[23];
    const int* ent_idx = (const int*)d_in[24];
    /* relation_indices d_in[25] unused */
    const int* tst_idx = (const int*)d_in[26];
    const int* ei      = (const int*)d_in[27];
    float* out = (float*)d_out;

    // Resolve REAL device addresses of the __device__ scratch arrays.
    // (Passing the symbol directly from host code passes the host shadow
    // address — that was the round-1 bug.)
    float *p_x, *p_xl1, *p_xr1, *p_out1, *p_xl2, *p_xr2;
    cudaGetSymbolAddress((void**)&p_x,    g_x);
    cudaGetSymbolAddress((void**)&p_xl1,  g_xl1);
    cudaGetSymbolAddress((void**)&p_xr1,  g_xr1);
    cudaGetSymbolAddress((void**)&p_out1, g_out1);
    cudaGetSymbolAddress((void**)&p_xl2,  g_xl2);
    cudaGetSymbolAddress((void**)&p_xr2,  g_xr2);

    const int TPB = 256;
    init_kernel<<<(Nn * HC + TPB - 1) / TPB, TPB>>>(out);
    build_x<<<(Nn * DIN + TPB - 1) / TPB, TPB>>>(ts, ent_tab, tst_tab, ent_idx, tst_idx);

    dim3 g1(1, (Nn + 63) / 64);
    gemm_bias<64, 128, 16, 8, 4><<<g1, 256>>>(p_x, Wl1, bl1, p_xl1, Nn, 256, 128);
    gemm_bias<64, 128, 16, 8, 4><<<g1, 256>>>(p_x, Wr1, br1, p_xr1, Nn, 256, 128);

    int edgeBlocks = (ET * 32 + TPB - 1) / TPB;
    edge_e1<<<edgeBlocks, TPB>>>(ei, att1);
    exp1<<<(ET * 4 + TPB - 1) / TPB, TPB>>>(ei);
    agg1<<<edgeBlocks, TPB>>>(ei);
    relu_bias1<<<(Nn * HC + TPB - 1) / TPB, TPB>>>(bias1);

    gemm_bias<64, 32, 16, 8, 1><<<g1, 256>>>(p_out1, Wl2, bl2, p_xl2, Nn, 128, 32);
    gemm_bias<64, 32, 16, 8, 1><<<g1, 256>>>(p_out1, Wr2, br2, p_xr2, Nn, 128, 32);

    edge_e2<<<edgeBlocks, TPB>>>(ei, att2);
    exp2<<<(ET + TPB - 1) / TPB, TPB>>>(ei);
    agg2<<<edgeBlocks, TPB>>>(ei, out + OFF_CAUS);

    bias_reg<<<(Nn * 32 + TPB - 1) / TPB, TPB>>>(out + OFF_CAUS, bias2, out + OFF_REG);

    vae_kernel<<<(Nn + 127) / 128, 128>>>(ts, eps, We1, be1, We2, be2, Wd1, bd1, Wd2, bd2, out);
}

// round 3
// speedup vs baseline: 1.6010x; 1.6010x over previous
#include <cuda_runtime.h>
#include <math.h>

#define Nn 50000
#define Ee 800000
#define ET (Ee + Nn)      // edges + self loops
#define DIN 256
#define HC 128            // H*C layer1 width
#define OUT2 32
#define LAT 16

// output layout (floats)
#define OFF_CAUS   0
#define OFF_Z      (Nn*32)
#define OFF_MEAN   (Nn*48)
#define OFF_LOGVAR (Nn*64)
#define OFF_XREC   (Nn*80)
#define OFF_REG    (Nn*208)

// ---------------- scratch (static device globals; no allocation) -------------
__device__ float g_x[(size_t)Nn * DIN];
__device__ float g_xl1[(size_t)Nn * HC];
__device__ float g_xr1[(size_t)Nn * HC];
__device__ float g_h[(size_t)Nn * HC];
__device__ float g_xl2[Nn * OUT2];
__device__ float g_xr2[Nn * OUT2];
__device__ int   g_cnt[Nn];        // histogram, then scatter cursor
__device__ int   g_rowptr[Nn + 1];
__device__ int   g_bsum[256];
__device__ int   g_srcs[ET];

__device__ __forceinline__ float lrelu(float v) { return v > 0.f ? v : 0.2f * v; }

// ---------------- init ----------------
__global__ void init_kernel(float* out) {
    int i = blockIdx.x * blockDim.x + threadIdx.x;
    if (i < Nn) g_cnt[i] = 0;
    if (i == 0) out[OFF_REG] = 0.f;
}

// ---------------- build concat input (float4) ----------------
__global__ void build_x(const float* __restrict__ ts, const float* __restrict__ ent_tab,
                        const float* __restrict__ tst_tab, const int* __restrict__ ent_idx,
                        const int* __restrict__ tst_idx) {
    int i = blockIdx.x * blockDim.x + threadIdx.x;   // float4 index
    if (i >= Nn * DIN / 4) return;
    int n = i >> 6;        // 64 float4 per row
    int c4 = i & 63;
    float4 v;
    if (c4 < 32)      v = ((const float4*)ts)[(size_t)n * 32 + c4];
    else if (c4 < 48) v = ((const float4*)ent_tab)[(size_t)ent_idx[n] * 16 + (c4 - 32)];
    else              v = ((const float4*)tst_tab)[(size_t)tst_idx[n] * 16 + (c4 - 48)];
    ((float4*)g_x)[i] = v;
}

// ---------------- CSR build ----------------
__global__ void hist_kernel(const int* __restrict__ ei) {
    int i = blockIdx.x * blockDim.x + threadIdx.x;
    if (i >= ET) return;
    int d = (i < Ee) ? ei[Ee + i] : i - Ee;
    atomicAdd(&g_cnt[d], 1);
}

__global__ void scan1_kernel() {   // per-block exclusive scan of g_cnt
    __shared__ int s[256];
    int t = threadIdx.x;
    int i = blockIdx.x * 256 + t;
    int v = (i < Nn) ? g_cnt[i] : 0;
    s[t] = v; __syncthreads();
    for (int off = 1; off < 256; off <<= 1) {
        int x = (t >= off) ? s[t - off] : 0;
        __syncthreads();
        s[t] += x;
        __syncthreads();
    }
    if (i < Nn) g_rowptr[i] = s[t] - v;
    if (t == 255) g_bsum[blockIdx.x] = s[255];
}

__global__ void scan2_kernel(int nb) {  // single block: exclusive scan of block sums
    __shared__ int s[256];
    int t = threadIdx.x;
    int v = (t < nb) ? g_bsum[t] : 0;
    s[t] = v; __syncthreads();
    for (int off = 1; off < 256; off <<= 1) {
        int x = (t >= off) ? s[t - off] : 0;
        __syncthreads();
        s[t] += x;
        __syncthreads();
    }
    if (t < nb) g_bsum[t] = s[t] - v;
}

__global__ void scan3_kernel() {
    int i = blockIdx.x * blockDim.x + threadIdx.x;
    if (i < Nn) {
        int r = g_rowptr[i] + g_bsum[i >> 8];
        g_rowptr[i] = r;
        g_cnt[i] = r;          // scatter cursor
    }
    if (i == 0) g_rowptr[Nn] = ET;
}

__global__ void scatter_kernel(const int* __restrict__ ei) {
    int i = blockIdx.x * blockDim.x + threadIdx.x;
    if (i >= ET) return;
    int s, d;
    if (i < Ee) { s = ei[i]; d = ei[Ee + i]; } else { s = i - Ee; d = s; }
    int pos = atomicAdd(&g_cnt[d], 1);
    g_srcs[pos] = s;
}

// ---------------- dual-weight tiled fp32 GEMM (256 threads) ------------------
// C = A[M,K] @ W[K,BN] + bias ; blockIdx.x selects (W0,b0,C0) or (W1,b1,C1)
template <int BM, int BN, int BK, int TM, int TN>
__global__ void gemm_dual(const float* __restrict__ A,
                          const float* __restrict__ W0, const float* __restrict__ b0, float* __restrict__ C0,
                          const float* __restrict__ W1, const float* __restrict__ b1, float* __restrict__ C1,
                          int M, int K) {
    const float* W    = blockIdx.x ? W1 : W0;
    const float* bias = blockIdx.x ? b1 : b0;
    float*       C    = blockIdx.x ? C1 : C0;
    __shared__ float As[BK][BM + 4];
    __shared__ float Ws[BK][BN];
    const int tid = threadIdx.x;
    const int NTX = BN / TN;
    const int tx = tid % NTX;
    const int ty = tid / NTX;
    const int row0 = blockIdx.y * BM;
    float acc[TM][TN];
#pragma unroll
    for (int i = 0; i < TM; i++)
#pragma unroll
        for (int j = 0; j < TN; j++) acc[i][j] = 0.f;

    for (int k0 = 0; k0 < K; k0 += BK) {
#pragma unroll
        for (int l = 0; l < BM * BK / 1024; l++) {
            int fid = tid + l * 256;
            int r = fid / (BK / 4), kq = fid % (BK / 4);
            int row = row0 + r;
            float4 v = (row < M) ? *(const float4*)&A[(size_t)row * K + k0 + kq * 4]
                                 : make_float4(0.f, 0.f, 0.f, 0.f);
            As[kq * 4 + 0][r] = v.x; As[kq * 4 + 1][r] = v.y;
            As[kq * 4 + 2][r] = v.z; As[kq * 4 + 3][r] = v.w;
        }
#pragma unroll
        for (int l = 0; l < BK * BN / 1024; l++) {
            int fid = tid + l * 256;
            int r = fid / (BN / 4), cq = fid % (BN / 4);
            *(float4*)&Ws[r][cq * 4] = *(const float4*)&W[(size_t)(k0 + r) * BN + cq * 4];
        }
        __syncthreads();
#pragma unroll
        for (int kk = 0; kk < BK; kk++) {
            float a[TM], b[TN];
#pragma unroll
            for (int i = 0; i < TM; i += 4) *(float4*)&a[i] = *(float4*)&As[kk][ty * TM + i];
#pragma unroll
            for (int j = 0; j < TN; j += 4) *(float4*)&b[j] = *(float4*)&Ws[kk][tx * TN + j];
#pragma unroll
            for (int i = 0; i < TM; i++)
#pragma unroll
                for (int j = 0; j < TN; j++) acc[i][j] += a[i] * b[j];
        }
        __syncthreads();
    }
#pragma unroll
    for (int i = 0; i < TM; i++) {
        int row = row0 + ty * TM + i;
        if (row < M) {
#pragma unroll
            for (int j = 0; j < TN; j += 4) {
                int col = tx * TN + j;
                float4 o;
                o.x = acc[i][j + 0] + bias[col + 0];
                o.y = acc[i][j + 1] + bias[col + 1];
                o.z = acc[i][j + 2] + bias[col + 2];
                o.w = acc[i][j + 3] + bias[col + 3];
                *(float4*)&C[(size_t)row * BN + col] = o;
            }
        }
    }
}

// ---------------- fused GAT layer 1 (warp per dst, online softmax) -----------
__global__ void gat1_fused(const float* __restrict__ att1, const float* __restrict__ bias1) {
    int gw = (blockIdx.x * blockDim.x + threadIdx.x) >> 5;
    int lane = threadIdx.x & 31;
    if (gw >= Nn) return;
    int d = gw;
    float4 xr = *(const float4*)&g_xr1[(size_t)d * HC + lane * 4];
    float4 av = *(const float4*)&att1[lane * 4];
    int e0 = g_rowptr[d], e1 = g_rowptr[d + 1];
    float m = -INFINITY, den = 0.f;
    float4 acc = make_float4(0.f, 0.f, 0.f, 0.f);
    for (int e = e0; e < e1; e++) {
        int s = g_srcs[e];
        float4 xl = *(const float4*)&g_xl1[(size_t)s * HC + lane * 4];
        float p = lrelu(xl.x + xr.x) * av.x + lrelu(xl.y + xr.y) * av.y +
                  lrelu(xl.z + xr.z) * av.z + lrelu(xl.w + xr.w) * av.w;
        // reduce within 8-lane head group (butterfly: all lanes get the head sum)
        p += __shfl_xor_sync(0xffffffffu, p, 1);
        p += __shfl_xor_sync(0xffffffffu, p, 2);
        p += __shfl_xor_sync(0xffffffffu, p, 4);
        float mn = fmaxf(m, p);
        float sc = __expf(m - mn);
        float wg = __expf(p - mn);
        den = den * sc + wg;
        acc.x = acc.x * sc + wg * xl.x;
        acc.y = acc.y * sc + wg * xl.y;
        acc.z = acc.z * sc + wg * xl.z;
        acc.w = acc.w * sc + wg * xl.w;
        m = mn;
    }
    float inv = 1.f / den;
    int c = lane * 4;
    float4 o;
    o.x = fmaxf(acc.x * inv + bias1[c + 0], 0.f);
    o.y = fmaxf(acc.y * inv + bias1[c + 1], 0.f);
    o.z = fmaxf(acc.z * inv + bias1[c + 2], 0.f);
    o.w = fmaxf(acc.w * inv + bias1[c + 3], 0.f);
    *(float4*)&g_h[(size_t)d * HC + c] = o;
}

// ---------------- fused GAT layer 2 + bias + L2 reg ----------------
__global__ void gat2_fused(const float* __restrict__ att2, const float* __restrict__ bias2,
                           float* __restrict__ caus, float* __restrict__ reg) {
    __shared__ float sred[8];
    int gw = (blockIdx.x * blockDim.x + threadIdx.x) >> 5;
    int lane = threadIdx.x & 31;
    float ssq = 0.f;
    if (gw < Nn) {
        int d = gw;
        float xr = g_xr2[d * 32 + lane];
        float at = att2[lane];
        int e0 = g_rowptr[d], e1 = g_rowptr[d + 1];
        float m = -INFINITY, den = 0.f, acc = 0.f;
        for (int e = e0; e < e1; e++) {
            int s = g_srcs[e];
            float xl = g_xl2[s * 32 + lane];
            float p = lrelu(xl + xr) * at;
            p += __shfl_xor_sync(0xffffffffu, p, 1);
            p += __shfl_xor_sync(0xffffffffu, p, 2);
            p += __shfl_xor_sync(0xffffffffu, p, 4);
            p += __shfl_xor_sync(0xffffffffu, p, 8);
            p += __shfl_xor_sync(0xffffffffu, p, 16);
            float mn = fmaxf(m, p);
            float sc = __expf(m - mn);
            float wg = __expf(p - mn);
            den = den * sc + wg;
            acc = acc * sc + wg * xl;
            m = mn;
        }
        float v = acc / den + bias2[lane];
        caus[d * 32 + lane] = v;
        ssq = v * v;
    }
    float t = ssq;
#pragma unroll
    for (int off = 16; off; off >>= 1) t += __shfl_xor_sync(0xffffffffu, t, off);
    if (lane == 0) sred[threadIdx.x >> 5] = t;
    __syncthreads();
    if (threadIdx.x < 8) {
        float u = sred[threadIdx.x];
#pragma unroll
        for (int off = 4; off; off >>= 1) u += __shfl_xor_sync(0xffu, u, off);
        if (threadIdx.x == 0) atomicAdd(reg, 0.01f * u);
    }
}

// ---------------- VAE (thread per node, weights in shared) ----------------
__global__ void vae_kernel(const float* __restrict__ ts, const float* __restrict__ eps,
                           const float* __restrict__ We1, const float* __restrict__ be1,
                           const float* __restrict__ We2, const float* __restrict__ be2,
                           const float* __restrict__ Wd1, const float* __restrict__ bd1,
                           const float* __restrict__ Wd2, const float* __restrict__ bd2,
                           float* __restrict__ out) {
    __shared__ float sWe1[128 * 32];
    __shared__ float sWe2[32 * 32];
    __shared__ float sWd1[16 * 32];
    __shared__ float sWd2[32 * 128];
    __shared__ float sbe1[32], sbe2[32], sbd1[32], sbd2[128];
    int tid = threadIdx.x;
    for (int i = tid; i < 128 * 32; i += blockDim.x) sWe1[i] = We1[i];
    for (int i = tid; i < 32 * 32; i += blockDim.x) sWe2[i] = We2[i];
    for (int i = tid; i < 16 * 32; i += blockDim.x) sWd1[i] = Wd1[i];
    for (int i = tid; i < 32 * 128; i += blockDim.x) sWd2[i] = Wd2[i];
    if (tid < 32) { sbe1[tid] = be1[tid]; sbe2[tid] = be2[tid]; sbd1[tid] = bd1[tid]; }
    for (int i = tid; i < 128; i += blockDim.x) sbd2[i] = bd2[i];
    __syncthreads();

    int node = blockIdx.x * blockDim.x + tid;
    if (node >= Nn) return;

    float h1[32];
#pragma unroll
    for (int j = 0; j < 32; j++) h1[j] = sbe1[j];
    const float* tsrow = ts + (size_t)node * 128;
    for (int k = 0; k < 128; k++) {
        float t = tsrow[k];
#pragma unroll
        for (int j = 0; j < 32; j++) h1[j] += t * sWe1[k * 32 + j];
    }
#pragma unroll
    for (int j = 0; j < 32; j++) h1[j] = h1[j] > 0.f ? h1[j] : 0.f;

    float q[32];
#pragma unroll
    for (int j = 0; j < 32; j++) q[j] = sbe2[j];
#pragma unroll
    for (int k = 0; k < 32; k++) {
        float t = h1[k];
#pragma unroll
        for (int j = 0; j < 32; j++) q[j] += t * sWe2[k * 32 + j];
    }

    float z[16];
#pragma unroll
    for (int l = 0; l < 16; l++) {
        float mean = q[l], lv = q[16 + l];
        float std = expf(0.5f * lv);
        z[l] = mean + std * eps[(size_t)node * 16 + l];
        out[OFF_MEAN + node * 16 + l] = mean;
        out[OFF_LOGVAR + node * 16 + l] = lv;
        out[OFF_Z + node * 16 + l] = z[l];
    }

    float h2[32];
#pragma unroll
    for (int j = 0; j < 32; j++) h2[j] = sbd1[j];
#pragma unroll
    for (int k = 0; k < 16; k++) {
        float t = z[k];
#pragma unroll
        for (int j = 0; j < 32; j++) h2[j] += t * sWd1[k * 32 + j];
    }
#pragma unroll
    for (int j = 0; j < 32; j++) h2[j] = h2[j] > 0.f ? h2[j] : 0.f;

    float* xr = out + OFF_XREC + (size_t)node * 128;
    for (int j = 0; j < 128; j++) {
        float acc = sbd2[j];
#pragma unroll
        for (int k = 0; k < 32; k++) acc += h2[k] * sWd2[k * 128 + j];
        xr[j] = acc;
    }
}

// ---------------- launch ----------------
extern "C" void kernel_launch(void* const* d_in, const int* in_sizes, int n_in,
                              void* d_out, int out_size) {
    const float* ts      = (const float*)d_in[0];
    const float* eps     = (const float*)d_in[1];
    const float* ent_tab = (const float*)d_in[2];
    const float* tst_tab = (const float*)d_in[3];
    const float* Wl1  = (const float*)d_in[4];
    const float* bl1  = (const float*)d_in[5];
    const float* Wr1  = (const float*)d_in[6];
    const float* br1  = (const float*)d_in[7];
    const float* att1 = (const float*)d_in[8];
    const float* bias1= (const float*)d_in[9];
    const float* Wl2  = (const float*)d_in[10];
    const float* bl2  = (const float*)d_in[11];
    const float* Wr2  = (const float*)d_in[12];
    const float* br2  = (const float*)d_in[13];
    const float* att2 = (const float*)d_in[14];
    const float* bias2= (const float*)d_in[15];
    const float* We1  = (const float*)d_in[16];
    const float* be1  = (const float*)d_in[17];
    const float* We2  = (const float*)d_in[18];
    const float* be2  = (const float*)d_in[19];
    const float* Wd1  = (const float*)d_in[20];
    const float* bd1  = (const float*)d_in[21];
    const float* Wd2  = (const float*)d_in[22];
    const float* bd2  = (const float*)d_in[23];
    const int* ent_idx = (const int*)d_in[24];
    const int* tst_idx = (const int*)d_in[26];
    const int* ei      = (const int*)d_in[27];
    float* out = (float*)d_out;

    // real device addresses of the __device__ scratch arrays
    float *p_x, *p_xl1, *p_xr1, *p_h, *p_xl2, *p_xr2;
    cudaGetSymbolAddress((void**)&p_x,   g_x);
    cudaGetSymbolAddress((void**)&p_xl1, g_xl1);
    cudaGetSymbolAddress((void**)&p_xr1, g_xr1);
    cudaGetSymbolAddress((void**)&p_h,   g_h);
    cudaGetSymbolAddress((void**)&p_xl2, g_xl2);
    cudaGetSymbolAddress((void**)&p_xr2, g_xr2);

    const int TPB = 256;
    const int nScanBlocks = (Nn + 255) / 256;          // 196
    const int edgeBlocks  = (ET + TPB - 1) / TPB;      // 3321

    init_kernel<<<nScanBlocks, TPB>>>(out);
    build_x<<<(Nn * DIN / 4 + TPB - 1) / TPB, TPB>>>(ts, ent_tab, tst_tab, ent_idx, tst_idx);

    // CSR build
    hist_kernel<<<edgeBlocks, TPB>>>(ei);
    scan1_kernel<<<nScanBlocks, 256>>>();
    scan2_kernel<<<1, 256>>>(nScanBlocks);
    scan3_kernel<<<nScanBlocks, 256>>>();
    scatter_kernel<<<edgeBlocks, TPB>>>(ei);

    // layer 1 projections (both weights in one launch)
    gemm_dual<128, 128, 16, 8, 8><<<dim3(2, (Nn + 127) / 128), 256>>>(
        p_x, Wl1, bl1, p_xl1, Wr1, br1, p_xr1, Nn, 256);

    // fused GAT layer 1 (+relu+bias)
    gat1_fused<<<(Nn * 32 + TPB - 1) / TPB, TPB>>>(att1, bias1);

    // layer 2 projections
    gemm_dual<128, 32, 32, 4, 4><<<dim3(2, (Nn + 127) / 128), 256>>>(
        p_h, Wl2, bl2, p_xl2, Wr2, br2, p_xr2, Nn, 128);

    // fused GAT layer 2 (+bias+reg)
    gat2_fused<<<(Nn * 32 + TPB - 1) / TPB, TPB>>>(att2, bias2, out + OFF_CAUS, out + OFF_REG);

    // VAE
    vae_kernel<<<(Nn + 127) / 128, 128>>>(ts, eps, We1, be1, We2, be2, Wd1, bd1, Wd2, bd2, out);
}

// round 4
// speedup vs baseline: 2.0702x; 1.2931x over previous
#include <cuda_runtime.h>
#include <math.h>

#define Nn 50000
#define Ee 800000
#define ET (Ee + Nn)      // edges + self loops
#define DIN 256
#define HC 128            // H*C layer1 width
#define OUT2 32
#define LAT 16

// output layout (floats)
#define OFF_CAUS   0
#define OFF_Z      (Nn*32)
#define OFF_MEAN   (Nn*48)
#define OFF_LOGVAR (Nn*64)
#define OFF_XREC   (Nn*80)
#define OFF_REG    (Nn*208)

// ---------------- scratch (static device globals; no allocation) -------------
__device__ float g_x[(size_t)Nn * DIN];
__device__ float g_xl1[(size_t)Nn * HC];
__device__ float g_xr1[(size_t)Nn * HC];
__device__ float g_h[(size_t)Nn * HC];
__device__ float g_xl2[Nn * OUT2];
__device__ float g_xr2[Nn * OUT2];
__device__ int   g_cnt[Nn];        // histogram, then scatter cursor
__device__ int   g_rowptr[Nn + 1];
__device__ int   g_bsum[256];
__device__ int   g_srcs[ET];

__device__ __forceinline__ float lrelu(float v) { return v > 0.f ? v : 0.2f * v; }

// ---- Blackwell packed fp32 math (fma.rn.f32x2: 2 FMAs per issue) ----
__device__ __forceinline__ unsigned long long pack2(float x, float y) {
    unsigned long long r;
    asm("mov.b64 %0,{%1,%2};" : "=l"(r) : "f"(x), "f"(y));
    return r;
}
__device__ __forceinline__ void fma2(unsigned long long& d, unsigned long long a,
                                     unsigned long long b) {
    asm("fma.rn.f32x2 %0,%1,%2,%0;" : "+l"(d) : "l"(a), "l"(b));
}

// ---------------- init ----------------
__global__ void init_kernel(float* out) {
    int i = blockIdx.x * blockDim.x + threadIdx.x;
    if (i < Nn) g_cnt[i] = 0;
    if (i == 0) out[OFF_REG] = 0.f;
}

// ---------------- build concat input (float4) ----------------
__global__ void build_x(const float* __restrict__ ts, const float* __restrict__ ent_tab,
                        const float* __restrict__ tst_tab, const int* __restrict__ ent_idx,
                        const int* __restrict__ tst_idx) {
    int i = blockIdx.x * blockDim.x + threadIdx.x;   // float4 index
    if (i >= Nn * DIN / 4) return;
    int n = i >> 6;        // 64 float4 per row
    int c4 = i & 63;
    float4 v;
    if (c4 < 32)      v = ((const float4*)ts)[(size_t)n * 32 + c4];
    else if (c4 < 48) v = ((const float4*)ent_tab)[(size_t)ent_idx[n] * 16 + (c4 - 32)];
    else              v = ((const float4*)tst_tab)[(size_t)tst_idx[n] * 16 + (c4 - 48)];
    ((float4*)g_x)[i] = v;
}

// ---------------- CSR build ----------------
__global__ void hist_kernel(const int* __restrict__ ei) {
    int i = blockIdx.x * blockDim.x + threadIdx.x;
    if (i >= ET) return;
    int d = (i < Ee) ? ei[Ee + i] : i - Ee;
    atomicAdd(&g_cnt[d], 1);
}

__global__ void scan1_kernel() {   // per-block exclusive scan of g_cnt
    __shared__ int s[256];
    int t = threadIdx.x;
    int i = blockIdx.x * 256 + t;
    int v = (i < Nn) ? g_cnt[i] : 0;
    s[t] = v; __syncthreads();
    for (int off = 1; off < 256; off <<= 1) {
        int x = (t >= off) ? s[t - off] : 0;
        __syncthreads();
        s[t] += x;
        __syncthreads();
    }
    if (i < Nn) g_rowptr[i] = s[t] - v;
    if (t == 255) g_bsum[blockIdx.x] = s[255];
}

__global__ void scan2_kernel(int nb) {  // single block: exclusive scan of block sums
    __shared__ int s[256];
    int t = threadIdx.x;
    int v = (t < nb) ? g_bsum[t] : 0;
    s[t] = v; __syncthreads();
    for (int off = 1; off < 256; off <<= 1) {
        int x = (t >= off) ? s[t - off] : 0;
        __syncthreads();
        s[t] += x;
        __syncthreads();
    }
    if (t < nb) g_bsum[t] = s[t] - v;
}

__global__ void scan3_kernel() {
    int i = blockIdx.x * blockDim.x + threadIdx.x;
    if (i < Nn) {
        int r = g_rowptr[i] + g_bsum[i >> 8];
        g_rowptr[i] = r;
        g_cnt[i] = r;          // scatter cursor
    }
    if (i == 0) g_rowptr[Nn] = ET;
}

__global__ void scatter_kernel(const int* __restrict__ ei) {
    int i = blockIdx.x * blockDim.x + threadIdx.x;
    if (i >= ET) return;
    int s, d;
    if (i < Ee) { s = ei[i]; d = ei[Ee + i]; } else { s = i - Ee; d = s; }
    int pos = atomicAdd(&g_cnt[d], 1);
    g_srcs[pos] = s;
}

// ---------------- dual-weight fp32x2 GEMM (256 threads) ----------------------
// C = A[M,K] @ W[K,BN] + bias ; blockIdx.x selects (W0,b0,C0) or (W1,b1,C1)
// A tile stored in SMEM with each value DUPLICATED into a u64 so the inner
// loop is pure LDS.128 + fma.rn.f32x2 (2 FMAs per issued instruction).
template <int BM, int BN, int BK, int TM, int TN>
__global__ void gemm_dual(const float* __restrict__ A,
                          const float* __restrict__ W0, const float* __restrict__ b0, float* __restrict__ C0,
                          const float* __restrict__ W1, const float* __restrict__ b1, float* __restrict__ C1,
                          int M, int K) {
    const float* W    = blockIdx.x ? W1 : W0;
    const float* bias = blockIdx.x ? b1 : b0;
    float*       C    = blockIdx.x ? C1 : C0;
    __shared__ __align__(16) unsigned long long As2[BK][BM + 2];
    __shared__ __align__(16) float Ws[BK][BN];
    const int tid = threadIdx.x;
    const int NTX = BN / TN;
    const int tx = tid % NTX;
    const int ty = tid / NTX;
    const int row0 = blockIdx.y * BM;
    unsigned long long acc2[TM][TN / 2];
#pragma unroll
    for (int i = 0; i < TM; i++)
#pragma unroll
        for (int j = 0; j < TN / 2; j++) acc2[i][j] = 0ull;

    for (int k0 = 0; k0 < K; k0 += BK) {
#pragma unroll
        for (int l = 0; l < BM * BK / 1024; l++) {
            int fid = tid + l * 256;
            int r = fid / (BK / 4), kq = fid % (BK / 4);
            int row = row0 + r;
            float4 v = (row < M) ? *(const float4*)&A[(size_t)row * K + k0 + kq * 4]
                                 : make_float4(0.f, 0.f, 0.f, 0.f);
            As2[kq * 4 + 0][r] = pack2(v.x, v.x);
            As2[kq * 4 + 1][r] = pack2(v.y, v.y);
            As2[kq * 4 + 2][r] = pack2(v.z, v.z);
            As2[kq * 4 + 3][r] = pack2(v.w, v.w);
        }
#pragma unroll
        for (int l = 0; l < BK * BN / 1024; l++) {
            int fid = tid + l * 256;
            int r = fid / (BN / 4), cq = fid % (BN / 4);
            *(float4*)&Ws[r][cq * 4] = *(const float4*)&W[(size_t)(k0 + r) * BN + cq * 4];
        }
        __syncthreads();
#pragma unroll
        for (int kk = 0; kk < BK; kk++) {
            unsigned long long a2[TM], b2[TN / 2];
#pragma unroll
            for (int i = 0; i < TM; i += 2) {
                ulonglong2 t = *(const ulonglong2*)&As2[kk][ty * TM + i];
                a2[i] = t.x; a2[i + 1] = t.y;
            }
#pragma unroll
            for (int j = 0; j < TN / 2; j += 2) {
                ulonglong2 t = *(const ulonglong2*)&Ws[kk][tx * TN + 2 * j];
                b2[j] = t.x; b2[j + 1] = t.y;
            }
#pragma unroll
            for (int i = 0; i < TM; i++)
#pragma unroll
                for (int j = 0; j < TN / 2; j++) fma2(acc2[i][j], a2[i], b2[j]);
        }
        __syncthreads();
    }
#pragma unroll
    for (int i = 0; i < TM; i++) {
        int row = row0 + ty * TM + i;
        if (row < M) {
#pragma unroll
            for (int j = 0; j < TN / 2; j += 2) {
                int col = tx * TN + 2 * j;
                float2 f0 = *reinterpret_cast<float2*>(&acc2[i][j]);
                float2 f1 = *reinterpret_cast<float2*>(&acc2[i][j + 1]);
                float4 o;
                o.x = f0.x + bias[col + 0];
                o.y = f0.y + bias[col + 1];
                o.z = f1.x + bias[col + 2];
                o.w = f1.y + bias[col + 3];
                *(float4*)&C[(size_t)row * BN + col] = o;
            }
        }
    }
}

// ---------------- fused GAT layer 1 (warp per dst, online softmax, x2 unroll) -
__global__ void gat1_fused(const float* __restrict__ att1, const float* __restrict__ bias1) {
    int gw = (blockIdx.x * blockDim.x + threadIdx.x) >> 5;
    int lane = threadIdx.x & 31;
    if (gw >= Nn) return;
    int d = gw;
    float4 xr = *(const float4*)&g_xr1[(size_t)d * HC + lane * 4];
    float4 av = *(const float4*)&att1[lane * 4];
    int e0 = g_rowptr[d], e1 = g_rowptr[d + 1];
    float m = -INFINITY, den = 0.f;
    float4 acc = make_float4(0.f, 0.f, 0.f, 0.f);
    int e = e0;
    for (; e + 1 < e1; e += 2) {
        int s0 = g_srcs[e], s1 = g_srcs[e + 1];
        float4 xa = *(const float4*)&g_xl1[(size_t)s0 * HC + lane * 4];
        float4 xb = *(const float4*)&g_xl1[(size_t)s1 * HC + lane * 4];
        float pa = lrelu(xa.x + xr.x) * av.x + lrelu(xa.y + xr.y) * av.y +
                   lrelu(xa.z + xr.z) * av.z + lrelu(xa.w + xr.w) * av.w;
        float pb = lrelu(xb.x + xr.x) * av.x + lrelu(xb.y + xr.y) * av.y +
                   lrelu(xb.z + xr.z) * av.z + lrelu(xb.w + xr.w) * av.w;
        pa += __shfl_xor_sync(0xffffffffu, pa, 1);
        pb += __shfl_xor_sync(0xffffffffu, pb, 1);
        pa += __shfl_xor_sync(0xffffffffu, pa, 2);
        pb += __shfl_xor_sync(0xffffffffu, pb, 2);
        pa += __shfl_xor_sync(0xffffffffu, pa, 4);
        pb += __shfl_xor_sync(0xffffffffu, pb, 4);
        float mn = fmaxf(m, fmaxf(pa, pb));
        float sc = __expf(m - mn);
        float wa = __expf(pa - mn);
        float wb = __expf(pb - mn);
        den = den * sc + wa + wb;
        acc.x = acc.x * sc + wa * xa.x + wb * xb.x;
        acc.y = acc.y * sc + wa * xa.y + wb * xb.y;
        acc.z = acc.z * sc + wa * xa.z + wb * xb.z;
        acc.w = acc.w * sc + wa * xa.w + wb * xb.w;
        m = mn;
    }
    if (e < e1) {
        int s = g_srcs[e];
        float4 xl = *(const float4*)&g_xl1[(size_t)s * HC + lane * 4];
        float p = lrelu(xl.x + xr.x) * av.x + lrelu(xl.y + xr.y) * av.y +
                  lrelu(xl.z + xr.z) * av.z + lrelu(xl.w + xr.w) * av.w;
        p += __shfl_xor_sync(0xffffffffu, p, 1);
        p += __shfl_xor_sync(0xffffffffu, p, 2);
        p += __shfl_xor_sync(0xffffffffu, p, 4);
        float mn = fmaxf(m, p);
        float sc = __expf(m - mn);
        float wg = __expf(p - mn);
        den = den * sc + wg;
        acc.x = acc.x * sc + wg * xl.x;
        acc.y = acc.y * sc + wg * xl.y;
        acc.z = acc.z * sc + wg * xl.z;
        acc.w = acc.w * sc + wg * xl.w;
    }
    float inv = 1.f / den;
    int c = lane * 4;
    float4 o;
    o.x = fmaxf(acc.x * inv + bias1[c + 0], 0.f);
    o.y = fmaxf(acc.y * inv + bias1[c + 1], 0.f);
    o.z = fmaxf(acc.z * inv + bias1[c + 2], 0.f);
    o.w = fmaxf(acc.w * inv + bias1[c + 3], 0.f);
    *(float4*)&g_h[(size_t)d * HC + c] = o;
}

// ---------------- fused GAT layer 2 + bias + L2 reg (x2 unroll) --------------
__global__ void gat2_fused(const float* __restrict__ att2, const float* __restrict__ bias2,
                           float* __restrict__ caus, float* __restrict__ reg) {
    __shared__ float sred[8];
    int gw = (blockIdx.x * blockDim.x + threadIdx.x) >> 5;
    int lane = threadIdx.x & 31;
    float ssq = 0.f;
    if (gw < Nn) {
        int d = gw;
        float xr = g_xr2[d * 32 + lane];
        float at = att2[lane];
        int e0 = g_rowptr[d], e1 = g_rowptr[d + 1];
        float m = -INFINITY, den = 0.f, acc = 0.f;
        int e = e0;
        for (; e + 1 < e1; e += 2) {
            int s0 = g_srcs[e], s1 = g_srcs[e + 1];
            float xa = g_xl2[s0 * 32 + lane];
            float xb = g_xl2[s1 * 32 + lane];
            float pa = lrelu(xa + xr) * at;
            float pb = lrelu(xb + xr) * at;
#pragma unroll
            for (int off = 1; off < 32; off <<= 1) {
                pa += __shfl_xor_sync(0xffffffffu, pa, off);
                pb += __shfl_xor_sync(0xffffffffu, pb, off);
            }
            float mn = fmaxf(m, fmaxf(pa, pb));
            float sc = __expf(m - mn);
            float wa = __expf(pa - mn);
            float wb = __expf(pb - mn);
            den = den * sc + wa + wb;
            acc = acc * sc + wa * xa + wb * xb;
            m = mn;
        }
        if (e < e1) {
            int s = g_srcs[e];
            float xl = g_xl2[s * 32 + lane];
            float p = lrelu(xl + xr) * at;
#pragma unroll
            for (int off = 1; off < 32; off <<= 1) p += __shfl_xor_sync(0xffffffffu, p, off);
            float mn = fmaxf(m, p);
            float sc = __expf(m - mn);
            float wg = __expf(p - mn);
            den = den * sc + wg;
            acc = acc * sc + wg * xl;
        }
        float v = acc / den + bias2[lane];
        caus[d * 32 + lane] = v;
        ssq = v * v;
    }
    float t = ssq;
#pragma unroll
    for (int off = 16; off; off >>= 1) t += __shfl_xor_sync(0xffffffffu, t, off);
    if (lane == 0) sred[threadIdx.x >> 5] = t;
    __syncthreads();
    if (threadIdx.x < 8) {
        float u = sred[threadIdx.x];
#pragma unroll
        for (int off = 4; off; off >>= 1) u += __shfl_xor_sync(0xffu, u, off);
        if (threadIdx.x == 0) atomicAdd(reg, 0.01f * u);
    }
}

// ---------------- VAE (thread per node, packed f32x2 math) ----------------
__global__ void vae_kernel(const float* __restrict__ ts, const float* __restrict__ eps,
                           const float* __restrict__ We1, const float* __restrict__ be1,
                           const float* __restrict__ We2, const float* __restrict__ be2,
                           const float* __restrict__ Wd1, const float* __restrict__ bd1,
                           const float* __restrict__ Wd2, const float* __restrict__ bd2,
                           float* __restrict__ out) {
    __shared__ __align__(16) float sWe1[128 * 32];
    __shared__ __align__(16) float sWe2[32 * 32];
    __shared__ __align__(16) float sWd1[16 * 32];
    __shared__ __align__(16) float sWd2[32 * 128];
    __shared__ __align__(16) float sbe1[32];
    __shared__ __align__(16) float sbe2[32];
    __shared__ __align__(16) float sbd1[32];
    __shared__ __align__(16) float sbd2[128];
    int tid = threadIdx.x;
    for (int i = tid; i < 128 * 32; i += blockDim.x) sWe1[i] = We1[i];
    for (int i = tid; i < 32 * 32; i += blockDim.x) sWe2[i] = We2[i];
    for (int i = tid; i < 16 * 32; i += blockDim.x) sWd1[i] = Wd1[i];
    for (int i = tid; i < 32 * 128; i += blockDim.x) sWd2[i] = Wd2[i];
    if (tid < 32) { sbe1[tid] = be1[tid]; sbe2[tid] = be2[tid]; sbd1[tid] = bd1[tid]; }
    for (int i = tid; i < 128; i += blockDim.x) sbd2[i] = bd2[i];
    __syncthreads();

    int node = blockIdx.x * blockDim.x + tid;
    if (node >= Nn) return;

    // encoder layer 1: [128] -> [32] relu
    unsigned long long h1p[16];
#pragma unroll
    for (int j = 0; j < 16; j++) h1p[j] = *(const unsigned long long*)&sbe1[2 * j];
    const float* tsrow = ts + (size_t)node * 128;
    for (int k = 0; k < 128; k++) {
        float t = tsrow[k];
        unsigned long long t2 = pack2(t, t);
#pragma unroll
        for (int j = 0; j < 16; j++)
            fma2(h1p[j], t2, *(const unsigned long long*)&sWe1[k * 32 + 2 * j]);
    }
    unsigned long long h1d[32];   // relu'd, duplicated per value
#pragma unroll
    for (int j = 0; j < 16; j++) {
        float2 f = *reinterpret_cast<float2*>(&h1p[j]);
        float a = fmaxf(f.x, 0.f), b = fmaxf(f.y, 0.f);
        h1d[2 * j] = pack2(a, a);
        h1d[2 * j + 1] = pack2(b, b);
    }

    // encoder layer 2: [32] -> [32]
    unsigned long long qp[16];
#pragma unroll
    for (int j = 0; j < 16; j++) qp[j] = *(const unsigned long long*)&sbe2[2 * j];
#pragma unroll
    for (int k = 0; k < 32; k++)
#pragma unroll
        for (int j = 0; j < 16; j++)
            fma2(qp[j], h1d[k], *(const unsigned long long*)&sWe2[k * 32 + 2 * j]);
    float q[32];
#pragma unroll
    for (int j = 0; j < 16; j++) {
        float2 f = *reinterpret_cast<float2*>(&qp[j]);
        q[2 * j] = f.x; q[2 * j + 1] = f.y;
    }

    float z[16];
#pragma unroll
    for (int l = 0; l < 16; l++) {
        float mean = q[l], lv = q[16 + l];
        float std = expf(0.5f * lv);
        z[l] = mean + std * eps[(size_t)node * 16 + l];
        out[OFF_MEAN + node * 16 + l] = mean;
        out[OFF_LOGVAR + node * 16 + l] = lv;
        out[OFF_Z + node * 16 + l] = z[l];
    }

    // decoder layer 1: [16] -> [32] relu
    unsigned long long h2p[16];
#pragma unroll
    for (int j = 0; j < 16; j++) h2p[j] = *(const unsigned long long*)&sbd1[2 * j];
#pragma unroll
    for (int k = 0; k < 16; k++) {
        unsigned long long zk = pack2(z[k], z[k]);
#pragma unroll
        for (int j = 0; j < 16; j++)
            fma2(h2p[j], zk, *(const unsigned long long*)&sWd1[k * 32 + 2 * j]);
    }
    unsigned long long h2d[32];
#pragma unroll
    for (int j = 0; j < 16; j++) {
        float2 f = *reinterpret_cast<float2*>(&h2p[j]);
        float a = fmaxf(f.x, 0.f), b = fmaxf(f.y, 0.f);
        h2d[2 * j] = pack2(a, a);
        h2d[2 * j + 1] = pack2(b, b);
    }

    // decoder layer 2: [32] -> [128]
    float* xrow = out + OFF_XREC + (size_t)node * 128;
#pragma unroll
    for (int j4 = 0; j4 < 32; j4++) {
        unsigned long long a0 = *(const unsigned long long*)&sbd2[4 * j4];
        unsigned long long a1 = *(const unsigned long long*)&sbd2[4 * j4 + 2];
#pragma unroll
        for (int k = 0; k < 32; k++) {
            fma2(a0, h2d[k], *(const unsigned long long*)&sWd2[k * 128 + 4 * j4]);
            fma2(a1, h2d[k], *(const unsigned long long*)&sWd2[k * 128 + 4 * j4 + 2]);
        }
        float2 f0 = *reinterpret_cast<float2*>(&a0);
        float2 f1 = *reinterpret_cast<float2*>(&a1);
        float4 o; o.x = f0.x; o.y = f0.y; o.z = f1.x; o.w = f1.y;
        *(float4*)&xrow[4 * j4] = o;
    }
}

// ---------------- launch ----------------
extern "C" void kernel_launch(void* const* d_in, const int* in_sizes, int n_in,
                              void* d_out, int out_size) {
    const float* ts      = (const float*)d_in[0];
    const float* eps     = (const float*)d_in[1];
    const float* ent_tab = (const float*)d_in[2];
    const float* tst_tab = (const float*)d_in[3];
    const float* Wl1  = (const float*)d_in[4];
    const float* bl1  = (const float*)d_in[5];
    const float* Wr1  = (const float*)d_in[6];
    const float* br1  = (const float*)d_in[7];
    const float* att1 = (const float*)d_in[8];
    const float* bias1= (const float*)d_in[9];
    const float* Wl2  = (const float*)d_in[10];
    const float* bl2  = (const float*)d_in[11];
    const float* Wr2  = (const float*)d_in[12];
    const float* br2  = (const float*)d_in[13];
    const float* att2 = (const float*)d_in[14];
    const float* bias2= (const float*)d_in[15];
    const float* We1  = (const float*)d_in[16];
    const float* be1  = (const float*)d_in[17];
    const float* We2  = (const float*)d_in[18];
    const float* be2  = (const float*)d_in[19];
    const float* Wd1  = (const float*)d_in[20];
    const float* bd1  = (const float*)d_in[21];
    const float* Wd2  = (const float*)d_in[22];
    const float* bd2  = (const float*)d_in[23];
    const int* ent_idx = (const int*)d_in[24];
    const int* tst_idx = (const int*)d_in[26];
    const int* ei      = (const int*)d_in[27];
    float* out = (float*)d_out;

    // real device addresses of the __device__ scratch arrays
    float *p_x, *p_xl1, *p_xr1, *p_h, *p_xl2, *p_xr2;
    cudaGetSymbolAddress((void**)&p_x,   g_x);
    cudaGetSymbolAddress((void**)&p_xl1, g_xl1);
    cudaGetSymbolAddress((void**)&p_xr1, g_xr1);
    cudaGetSymbolAddress((void**)&p_h,   g_h);
    cudaGetSymbolAddress((void**)&p_xl2, g_xl2);
    cudaGetSymbolAddress((void**)&p_xr2, g_xr2);

    const int TPB = 256;
    const int nScanBlocks = (Nn + 255) / 256;          // 196
    const int edgeBlocks  = (ET + TPB - 1) / TPB;      // 3321

    init_kernel<<<nScanBlocks, TPB>>>(out);
    build_x<<<(Nn * DIN / 4 + TPB - 1) / TPB, TPB>>>(ts, ent_tab, tst_tab, ent_idx, tst_idx);

    // CSR build
    hist_kernel<<<edgeBlocks, TPB>>>(ei);
    scan1_kernel<<<nScanBlocks, 256>>>();
    scan2_kernel<<<1, 256>>>(nScanBlocks);
    scan3_kernel<<<nScanBlocks, 256>>>();
    scatter_kernel<<<edgeBlocks, TPB>>>(ei);

    // layer 1 projections (both weights in one launch, f32x2 math)
    gemm_dual<128, 128, 16, 8, 8><<<dim3(2, (Nn + 127) / 128), 256>>>(
        p_x, Wl1, bl1, p_xl1, Wr1, br1, p_xr1, Nn, 256);

    // fused GAT layer 1 (+relu+bias)
    gat1_fused<<<(Nn * 32 + TPB - 1) / TPB, TPB>>>(att1, bias1);

    // layer 2 projections
    gemm_dual<128, 32, 32, 4, 4><<<dim3(2, (Nn + 127) / 128), 256>>>(
        p_h, Wl2, bl2, p_xl2, Wr2, br2, p_xr2, Nn, 128);

    // fused GAT layer 2 (+bias+reg)
    gat2_fused<<<(Nn * 32 + TPB - 1) / TPB, TPB>>>(att2, bias2, out + OFF_CAUS, out + OFF_REG);

    // VAE
    vae_kernel<<<(Nn + 127) / 128, 128>>>(ts, eps, We1, be1, We2, be2, Wd1, bd1, Wd2, bd2, out);
}